// round 10
// baseline (speedup 1.0000x reference)
#include <cuda_runtime.h>

#define S 64
#define D 128
#define ALPHA 0.2f
#define NWARP 8

__device__ unsigned int g_ticket;

__global__ void reset_ticket_kernel() { g_ticket = 0u; }

__global__ void __launch_bounds__(256, 4)
gat_kernel(const float* __restrict__ center,
           const float* __restrict__ nbr,
           const float* __restrict__ a,
           float* __restrict__ out,
           int ngroups)
{
    __shared__ float s_m[NWARP];
    __shared__ float s_sum[NWARP];
    __shared__ float s_acc[NWARP][D];   // 4 KB
    __shared__ unsigned int s_g[2];     // double-buffered next-ticket

    const int tid  = threadIdx.x;
    const int warp = tid >> 5;
    const int lane = tid & 31;

    // a[0:128] pairs with center, a[128:256] with nbr (loop-invariant).
    const float4 a1 = reinterpret_cast<const float4*>(a)[lane];
    const float4 a2 = reinterpret_cast<const float4*>(a)[32 + lane];

    // First ticket.
    if (tid == 0) s_g[0] = atomicAdd(&g_ticket, 1u);
    __syncthreads();
    unsigned int g = s_g[0];
    int p = 1;

    while (g < (unsigned int)ngroups) {
        const float4* __restrict__ cvec =
            reinterpret_cast<const float4*>(center) + (size_t)g * (S * D / 4) + warp * 8 * 32;
        const float4* __restrict__ nvec =
            reinterpret_cast<const float4*>(nbr)    + (size_t)g * (S * D / 4) + warp * 8 * 32;

        // ---- Phase 1: burst-load 8 c rows + 8 v rows; partial dots per lane.
        float4 v[8];
        float  d[8];
        #pragma unroll
        for (int i = 0; i < 8; i++) {
            const float4 c = __ldcs(&cvec[i * 32 + lane]);
            v[i]           = __ldcs(&nvec[i * 32 + lane]);
            d[i] = c.x * a1.x + c.y * a1.y + c.z * a1.z + c.w * a1.w
                 + v[i].x * a2.x + v[i].y * a2.y + v[i].z * a2.z + v[i].w * a2.w;
        }

        // Prefetch next ticket; its 300-cycle latency hides under phases 2-3.
        if (tid == 0) s_g[p] = atomicAdd(&g_ticket, 1u);

        // ---- Phase 2: butterfly-reduce all 8 dots (off the load path). ----
        #pragma unroll
        for (int i = 0; i < 8; i++) {
            #pragma unroll
            for (int off = 16; off; off >>= 1)
                d[i] += __shfl_xor_sync(0xffffffffu, d[i], off);
        }

        // ---- Phase 3: per-warp softmax over 8 logits + weighted accumulate.
        float m = -1e30f;
        #pragma unroll
        for (int i = 0; i < 8; i++) {
            d[i] = (d[i] > 0.f) ? d[i] : ALPHA * d[i];   // leaky relu
            m = fmaxf(m, d[i]);
        }
        float sm = 0.f;
        float4 acc = make_float4(0.f, 0.f, 0.f, 0.f);
        #pragma unroll
        for (int i = 0; i < 8; i++) {
            const float pw = __expf(d[i] - m);
            sm += pw;
            acc.x += pw * v[i].x;
            acc.y += pw * v[i].y;
            acc.z += pw * v[i].z;
            acc.w += pw * v[i].w;
        }

        __syncthreads();   // prev epilogue done with s_acc; also orders s_g[p]

        if (lane == 0) { s_m[warp] = m; s_sum[warp] = sm; }
        reinterpret_cast<float4*>(s_acc[warp])[lane] = acc;
        __syncthreads();

        // ---- Phase 4: cross-warp combine; 128 threads, one feature each. ----
        if (tid < D) {
            float M = s_m[0];
            #pragma unroll
            for (int w = 1; w < NWARP; w++) M = fmaxf(M, s_m[w]);

            float tot = 0.f, o = 0.f;
            #pragma unroll
            for (int w = 0; w < NWARP; w++) {
                const float f = __expf(s_m[w] - M);
                tot += s_sum[w] * f;
                o   += s_acc[w][tid] * f;
            }
            out[(size_t)g * D + tid] = o * __frcp_rn(tot);
        }

        g = s_g[p];        // written before barrier 1, read after barrier 2
        p ^= 1;
    }
}

extern "C" void kernel_launch(void* const* d_in, const int* in_sizes, int n_in,
                              void* d_out, int out_size)
{
    const float* center = (const float*)d_in[0];
    const float* nbr    = (const float*)d_in[1];
    const float* a      = (const float*)d_in[2];
    float* out          = (float*)d_out;

    const int ngroups = in_sizes[0] / (S * D);   // 8192

    int dev = 0, sms = 148;
    cudaGetDevice(&dev);
    cudaDeviceGetAttribute(&sms, cudaDevAttrMultiProcessorCount, dev);

    reset_ticket_kernel<<<1, 1>>>();
    gat_kernel<<<4 * sms, 256>>>(center, nbr, a, out, ngroups);
}

// round 12
// speedup vs baseline: 1.0054x; 1.0054x over previous
#include <cuda_runtime.h>

#define S 64
#define D 128
#define ALPHA 0.2f
#define NWARP 16
#define THREADS 512

__device__ unsigned int g_ticket;

__global__ void reset_ticket_kernel() { g_ticket = 0u; }

__global__ void __launch_bounds__(THREADS, 3)
gat_kernel(const float* __restrict__ center,
           const float* __restrict__ nbr,
           const float* __restrict__ a,
           float* __restrict__ out,
           int ngroups)
{
    __shared__ float s_m[NWARP];
    __shared__ float s_sum[NWARP];
    __shared__ float s_acc[NWARP][D];   // 8 KB
    __shared__ unsigned int s_g[2];     // double-buffered next-ticket

    const int tid  = threadIdx.x;
    const int warp = tid >> 5;
    const int lane = tid & 31;

    // a[0:128] pairs with center, a[128:256] with nbr (loop-invariant).
    const float4 a1 = reinterpret_cast<const float4*>(a)[lane];
    const float4 a2 = reinterpret_cast<const float4*>(a)[32 + lane];

    if (tid == 0) s_g[0] = atomicAdd(&g_ticket, 1u);
    __syncthreads();
    unsigned int g = s_g[0];
    int p = 1;

    while (g < (unsigned int)ngroups) {
        // Each warp owns 4 consecutive rows of the 64-row group.
        const float4* __restrict__ cvec =
            reinterpret_cast<const float4*>(center) + (size_t)g * (S * D / 4) + warp * 4 * 32;
        const float4* __restrict__ nvec =
            reinterpret_cast<const float4*>(nbr)    + (size_t)g * (S * D / 4) + warp * 4 * 32;

        // ---- Phase 1: burst-load 4 c rows + 4 v rows; partial dots per lane.
        float4 v[4];
        float  d[4];
        #pragma unroll
        for (int i = 0; i < 4; i++) {
            const float4 c = __ldcs(&cvec[i * 32 + lane]);
            v[i]           = __ldcs(&nvec[i * 32 + lane]);
            d[i] = c.x * a1.x + c.y * a1.y + c.z * a1.z + c.w * a1.w
                 + v[i].x * a2.x + v[i].y * a2.y + v[i].z * a2.z + v[i].w * a2.w;
        }

        // Prefetch next ticket; ATOMG latency hides under phases 2-3.
        if (tid == 0) s_g[p] = atomicAdd(&g_ticket, 1u);

        // ---- Phase 2: butterfly-reduce the 4 dots (off the load path). ----
        #pragma unroll
        for (int i = 0; i < 4; i++) {
            #pragma unroll
            for (int off = 16; off; off >>= 1)
                d[i] += __shfl_xor_sync(0xffffffffu, d[i], off);
        }

        // ---- Phase 3: per-warp softmax over 4 logits + weighted accumulate.
        float m = -1e30f;
        #pragma unroll
        for (int i = 0; i < 4; i++) {
            d[i] = (d[i] > 0.f) ? d[i] : ALPHA * d[i];   // leaky relu
            m = fmaxf(m, d[i]);
        }
        float sm = 0.f;
        float4 acc = make_float4(0.f, 0.f, 0.f, 0.f);
        #pragma unroll
        for (int i = 0; i < 4; i++) {
            const float pw = __expf(d[i] - m);
            sm += pw;
            acc.x += pw * v[i].x;
            acc.y += pw * v[i].y;
            acc.z += pw * v[i].z;
            acc.w += pw * v[i].w;
        }

        __syncthreads();   // prev epilogue done with s_acc; orders s_g[p]

        if (lane == 0) { s_m[warp] = m; s_sum[warp] = sm; }
        reinterpret_cast<float4*>(s_acc[warp])[lane] = acc;
        __syncthreads();

        // ---- Phase 4: cross-warp combine; 128 threads, one feature each. ----
        if (tid < D) {
            float M = s_m[0];
            #pragma unroll
            for (int w = 1; w < NWARP; w++) M = fmaxf(M, s_m[w]);

            float tot = 0.f, o = 0.f;
            #pragma unroll
            for (int w = 0; w < NWARP; w++) {
                const float f = __expf(s_m[w] - M);
                tot += s_sum[w] * f;
                o   += s_acc[w][tid] * f;
            }
            out[(size_t)g * D + tid] = o * __frcp_rn(tot);
        }

        g = s_g[p];        // written before barrier 1, read after barrier 2
        p ^= 1;
    }
}

extern "C" void kernel_launch(void* const* d_in, const int* in_sizes, int n_in,
                              void* d_out, int out_size)
{
    const float* center = (const float*)d_in[0];
    const float* nbr    = (const float*)d_in[1];
    const float* a      = (const float*)d_in[2];
    float* out          = (float*)d_out;

    const int ngroups = in_sizes[0] / (S * D);   // 8192

    int dev = 0, sms = 148;
    cudaGetDevice(&dev);
    cudaDeviceGetAttribute(&sms, cudaDevAttrMultiProcessorCount, dev);

    reset_ticket_kernel<<<1, 1>>>();
    gat_kernel<<<3 * sms, THREADS>>>(center, nbr, a, out, ngroups);
}